// round 9
// baseline (speedup 1.0000x reference)
#include <cuda_runtime.h>
#include <math_constants.h>

#define HID   64
#define MAXN  50000

// Per-node precomputed tables, stride 8 floats for float4 alignment.
// srcTab[n*8 + 0..3] = ps (x0·Wsp + bsp), [n*8+4] = gs (x·Wsg + bsg)
// dstTab[n*8 + 0..3] = pd (x0·Wdp),       [n*8+4] = gd (x·Wdg + bdg)
__device__ float g_srcTab[MAXN * 8];
__device__ float g_dstTab[MAXN * 8];

// Device-wide barrier state (sense-reversal; self-resetting => graph-replay safe)
__device__ unsigned g_count;            // zero-init, returns to zero each launch
__device__ volatile unsigned g_sense;

// One persistent kernel:
//   phase 1: node gate/param precompute (grid-stride) + zero accumulators
//   device-wide barrier
//   phase 2: edge loop (y dot + gate + pair potential + scatter + energy)
__global__ void __launch_bounds__(256, 4)
fused_kernel(const float* __restrict__ x,
             const float* __restrict__ x0,
             const float* __restrict__ y,
             const float* __restrict__ bondlength,
             const int* __restrict__ src,
             const int* __restrict__ dst,
             const float* __restrict__ Wsg, const float* __restrict__ bsg,
             const float* __restrict__ Wdg, const float* __restrict__ bdg,
             const float* __restrict__ Weg, const float* __restrict__ beg,
             const float* __restrict__ Wsp, const float* __restrict__ bsp,
             const float* __restrict__ Wdp,
             float* __restrict__ atom, float* __restrict__ out0,
             int N, int E, float invN)
{
    __shared__ float sWeg[HID];
    __shared__ float sEsum;
    const int tid = threadIdx.x;
    if (tid < HID) sWeg[tid] = Weg[tid];
    if (tid == 0)  sEsum = 0.0f;
    __syncthreads();

    const int sub = tid & 7;

    // ---------------- phase 1: per-node precompute ----------------
    {
        const int gridStride = gridDim.x * blockDim.x;
        const int total = N * 8;
        const int nIter = (total + gridStride - 1) / gridStride;
        for (int it = 0; it < nIter; ++it) {
            int t    = it * gridStride + blockIdx.x * blockDim.x + tid;
            int node = t >> 3;
            bool valid = (node < N);

            float gs = 0.f, gd = 0.f;
            float v[8];
#pragma unroll
            for (int p = 0; p < 8; p++) v[p] = 0.f;

            if (valid) {
                const size_t base = (size_t)node * HID;
                const int h0 = sub * 4;
                const int h1 = 32 + sub * 4;
                float4 xa  = *(const float4*)(x  + base + h0);
                float4 xb  = *(const float4*)(x  + base + h1);
                float4 x0a = *(const float4*)(x0 + base + h0);
                float4 x0b = *(const float4*)(x0 + base + h1);
                const float* xav  = (const float*)&xa;
                const float* xbv  = (const float*)&xb;
                const float* x0av = (const float*)&x0a;
                const float* x0bv = (const float*)&x0b;
#pragma unroll
                for (int k = 0; k < 4; k++) {
                    int ha = h0 + k, hb = h1 + k;
                    gs += xav[k] * __ldg(Wsg + ha) + xbv[k] * __ldg(Wsg + hb);
                    gd += xav[k] * __ldg(Wdg + ha) + xbv[k] * __ldg(Wdg + hb);
                    float4 wsa = *(const float4*)(Wsp + ha * 4);
                    float4 wsb = *(const float4*)(Wsp + hb * 4);
                    float4 wda = *(const float4*)(Wdp + ha * 4);
                    float4 wdb = *(const float4*)(Wdp + hb * 4);
                    v[0] += x0av[k] * wsa.x + x0bv[k] * wsb.x;
                    v[1] += x0av[k] * wsa.y + x0bv[k] * wsb.y;
                    v[2] += x0av[k] * wsa.z + x0bv[k] * wsb.z;
                    v[3] += x0av[k] * wsa.w + x0bv[k] * wsb.w;
                    v[4] += x0av[k] * wda.x + x0bv[k] * wdb.x;
                    v[5] += x0av[k] * wda.y + x0bv[k] * wdb.y;
                    v[6] += x0av[k] * wda.z + x0bv[k] * wdb.z;
                    v[7] += x0av[k] * wda.w + x0bv[k] * wdb.w;
                }
            }

            // transpose-reduce (7 shuffles): lane sub gets group-sum of v[sub]
            bool hi4 = (sub & 4) != 0;
            float a0k = hi4 ? v[4] : v[0], a0s = hi4 ? v[0] : v[4];
            float a1k = hi4 ? v[5] : v[1], a1s = hi4 ? v[1] : v[5];
            float a2k = hi4 ? v[6] : v[2], a2s = hi4 ? v[2] : v[6];
            float a3k = hi4 ? v[7] : v[3], a3s = hi4 ? v[3] : v[7];
            a0k += __shfl_xor_sync(0xffffffffu, a0s, 4);
            a1k += __shfl_xor_sync(0xffffffffu, a1s, 4);
            a2k += __shfl_xor_sync(0xffffffffu, a2s, 4);
            a3k += __shfl_xor_sync(0xffffffffu, a3s, 4);
            bool hi2 = (sub & 2) != 0;
            float b0k = hi2 ? a2k : a0k, b0s = hi2 ? a0k : a2k;
            float b1k = hi2 ? a3k : a1k, b1s = hi2 ? a1k : a3k;
            b0k += __shfl_xor_sync(0xffffffffu, b0s, 2);
            b1k += __shfl_xor_sync(0xffffffffu, b1s, 2);
            bool hi1 = (sub & 1) != 0;
            float ck = hi1 ? b1k : b0k, cs = hi1 ? b0k : b1k;
            ck += __shfl_xor_sync(0xffffffffu, cs, 1);

#pragma unroll
            for (int off = 4; off >= 1; off >>= 1) {
                gs += __shfl_xor_sync(0xffffffffu, gs, off);
                gd += __shfl_xor_sync(0xffffffffu, gd, off);
            }

            if (valid) {
                if (sub < 4)
                    g_srcTab[(size_t)node * 8 + sub] = ck + __ldg(bsp + sub);
                else
                    g_dstTab[(size_t)node * 8 + (sub - 4)] = ck;
                if (sub == 0) {
                    g_srcTab[(size_t)node * 8 + 4] = gs + __ldg(bsg);
                    g_dstTab[(size_t)node * 8 + 4] = gd + __ldg(bdg);
                    atom[node] = 0.0f;
                    if (node == 0) *out0 = 0.0f;
                }
            }
        }
    }

    // ---------------- device-wide barrier (sense reversal) ----------------
    __syncthreads();
    __threadfence();
    if (tid == 0) {
        unsigned s = g_sense;                  // read sense BEFORE arriving
        unsigned my = atomicAdd(&g_count, 1u);
        if (my == gridDim.x - 1) {
            g_count = 0;                       // self-reset for next replay
            __threadfence();
            g_sense = s ^ 1u;                  // release
        } else {
            while (g_sense == s) __nanosleep(64);
        }
    }
    __syncthreads();

    // ---------------- phase 2: edge loop ----------------
    const int grpInBlk = tid >> 3;             // 0..31
    const float4 wa = *(const float4*)(sWeg + sub * 4);
    const float4 wb = *(const float4*)(sWeg + 32 + sub * 4);
    const float begv = __ldg(beg);

    const int CHUNK = 256;
    const int nChunks = (E + CHUNK - 1) / CHUNK;

    float Vacc = 0.0f;
    int chunk = blockIdx.x;

    float r[8];
    if (chunk < nChunks) {
        int e0 = chunk * CHUNK + grpInBlk * 8;
#pragma unroll
        for (int p = 0; p < 8; p++)
            r[p] = (e0 + p < E) ? __ldg(bondlength + e0 + p) : 5.0f;
    }

    for (; chunk < nChunks; chunk += gridDim.x) {
        const int e0 = chunk * CHUNK + grpInBlk * 8;
        const float* ybase = y + (size_t)e0 * HID;

        // 1) y loads gated on resident r[] (evict-first stream)
        float d[8];
#pragma unroll
        for (int p = 0; p < 8; p += 2) {
            float da = 0.f, db = 0.f;
            if (r[p] <= 4.0f) {
                const float* row = ybase + (size_t)p * HID;
                float4 a = __ldcs((const float4*)(row + sub * 4));
                float4 b = __ldcs((const float4*)(row + 32 + sub * 4));
                da = a.x*wa.x + a.y*wa.y + a.z*wa.z + a.w*wa.w
                   + b.x*wb.x + b.y*wb.y + b.z*wb.z + b.w*wb.w;
            }
            if (r[p + 1] <= 4.0f) {
                const float* row = ybase + (size_t)(p + 1) * HID;
                float4 a = __ldcs((const float4*)(row + sub * 4));
                float4 b = __ldcs((const float4*)(row + 32 + sub * 4));
                db = a.x*wa.x + a.y*wa.y + a.z*wa.z + a.w*wa.w
                   + b.x*wb.x + b.y*wb.y + b.z*wb.z + b.w*wb.w;
            }
            d[p] = da; d[p + 1] = db;
        }

        // 2) tail-edge loads issued EARLY (independent of the shuffle reduce):
        //    lane sub owns edge e0+sub; its r is this thread's r[sub].
        float myr = r[0];
#pragma unroll
        for (int p = 1; p < 8; p++)
            if (sub == p) myr = r[p];
        int  e    = e0 + sub;
        bool tact = (e < E) && (myr <= 4.0f);
        int s_ = 0, dn = 0;
        float4 ps = make_float4(0.f, 0.f, 0.f, 0.f);
        float4 pd = make_float4(0.f, 0.f, 0.f, 0.f);
        float gsv = 0.f, gdv = 0.f;
        if (tact) {
            s_ = src[e];
            dn = dst[e];
            ps  = *(const float4*)(g_srcTab + (size_t)s_ * 8);
            gsv = g_srcTab[(size_t)s_ * 8 + 4];
            pd  = *(const float4*)(g_dstTab + (size_t)dn * 8);
            gdv = g_dstTab[(size_t)dn * 8 + 4];
        }

        // 3) prefetch NEXT chunk's bond lengths into r[]
        {
            int nchunk = chunk + gridDim.x;
            if (nchunk < nChunks) {
                int ne0 = nchunk * CHUNK + grpInBlk * 8;
#pragma unroll
                for (int p = 0; p < 8; p++)
                    r[p] = (ne0 + p < E) ? __ldg(bondlength + ne0 + p) : 5.0f;
            }
        }

        // 4) transpose-reduce (7 shuffles): lane sub gets dot of edge e0+sub
        bool hi4 = (sub & 4) != 0;
        float a0k = hi4 ? d[4] : d[0], a0s = hi4 ? d[0] : d[4];
        float a1k = hi4 ? d[5] : d[1], a1s = hi4 ? d[1] : d[5];
        float a2k = hi4 ? d[6] : d[2], a2s = hi4 ? d[2] : d[6];
        float a3k = hi4 ? d[7] : d[3], a3s = hi4 ? d[3] : d[7];
        a0k += __shfl_xor_sync(0xffffffffu, a0s, 4);
        a1k += __shfl_xor_sync(0xffffffffu, a1s, 4);
        a2k += __shfl_xor_sync(0xffffffffu, a2s, 4);
        a3k += __shfl_xor_sync(0xffffffffu, a3s, 4);
        bool hi2 = (sub & 2) != 0;
        float b0k = hi2 ? a2k : a0k, b0s = hi2 ? a0k : a2k;
        float b1k = hi2 ? a3k : a1k, b1s = hi2 ? a1k : a3k;
        b0k += __shfl_xor_sync(0xffffffffu, b0s, 2);
        b1k += __shfl_xor_sync(0xffffffffu, b1s, 2);
        bool hi1 = (sub & 1) != 0;
        float myd = hi1 ? b1k : b0k, cs = hi1 ? b0k : b1k;
        myd += __shfl_xor_sync(0xffffffffu, cs, 1);

        // 5) tail compute + scatter (gathers already in flight / done)
        if (tact) {
            float m  = gsv + gdv + myd + begv;
            float bo = 1.0f / (1.0f + __expf(-m));

            float p1 = __expf(ps.y + pd.y);
            float p3 = __expf(ps.w + pd.w);
            // p0*exp(-p1*r) == exp(a0 - p1*r); same for attract term
            float frep = __expf(ps.x + pd.x - p1 * myr);
            float fatt = __expf(ps.z + pd.z - p3 * myr);

            // cutoff: 1 for r<3.8; 0.5-0.5*sin(pi*(r-3.9)/0.2) in [3.8,4.0]
            float c = 1.0f;
            if (myr >= 3.8f)
                c = 0.5f - 0.5f * __sinf(CUDART_PI_F * (myr - 3.9f) * 5.0f);

            float V = c * (frep - bo * fatt);
            atomicAdd(atom + dn, V);
            Vacc += V;
        }
    }

    // once per block: energy accumulation
#pragma unroll
    for (int off = 16; off >= 1; off >>= 1)
        Vacc += __shfl_xor_sync(0xffffffffu, Vacc, off);
    if ((tid & 31) == 0 && Vacc != 0.0f)
        atomicAdd(&sEsum, Vacc);
    __syncthreads();
    if (tid == 0)
        atomicAdd(out0, sEsum * invN);
}

extern "C" void kernel_launch(void* const* d_in, const int* in_sizes, int n_in,
                              void* d_out, int out_size)
{
    const float* x    = (const float*)d_in[0];
    const float* x0   = (const float*)d_in[1];
    const float* y    = (const float*)d_in[2];
    const float* bond = (const float*)d_in[3];
    const int*   src  = (const int*)d_in[4];
    const int*   dst  = (const int*)d_in[5];
    const float* Wsg  = (const float*)d_in[6];
    const float* bsg  = (const float*)d_in[7];
    const float* Wdg  = (const float*)d_in[8];
    const float* bdg  = (const float*)d_in[9];
    const float* Weg  = (const float*)d_in[10];
    const float* beg  = (const float*)d_in[11];
    const float* Wsp  = (const float*)d_in[12];
    const float* bsp  = (const float*)d_in[13];
    const float* Wdp  = (const float*)d_in[14];

    const int N = in_sizes[0] / HID;   // 50000
    const int E = in_sizes[3];         // 1600000

    float* out = (float*)d_out;        // out[0] = energy, out[1..N] = atomwise

    // Persistent fused kernel. 148 SMs x 4 blocks; __launch_bounds__(256,4)
    // guarantees 4-block residency (64-reg cap), so the device barrier is safe
    // on both 148-SM and 152-SM sm_103a parts.
    const int grid = 148 * 4;
    fused_kernel<<<grid, 256>>>(x, x0, y, bond, src, dst,
                                Wsg, bsg, Wdg, bdg, Weg, beg, Wsp, bsp, Wdp,
                                out + 1, out, N, E, 1.0f / (float)N);
}